// round 16
// baseline (speedup 1.0000x reference)
#include <cuda_runtime.h>
#include <cuda_fp16.h>

#define NN 50000
#define EE 800000
#define HH 64
#define PP 20
#define GG 500
#define NB 391           // (NN+127)/128 gemm tiles
#define AGB 6250         // NN warps / 8 per block  (6250*8 == NN exactly)

// ---------------- device scratch ----------
__device__ float g_pe[NN * HH];                       // pe0 fp32 (layer1 input)
__device__ float g_h[NN * HH];                        // final conv5 output (BN/pool input)
__device__ __align__(16) __half2 g_tH[NN * 32];       // messages H
__device__ __align__(16) __half2 g_tP[NN * 32];       // messages P
__device__ __align__(16) __half2 g_hp[NN * 32];       // h+pe fp16 (gemm A part0)
__device__ __align__(16) __half2 g_pe16[NN * 32];     // pe fp16  (gemm A part1)
__device__ __align__(16) __half g_w16[7 * 4096];      // fp16 weights: Wc2..5, Wp1..3
__device__ float g_dinv[NN];
__device__ int   g_deg[NN];
__device__ int   g_offs[NN + 1];
__device__ int   g_cursor[NN];
__device__ int   g_csr[EE];
__device__ int   g_bsum[64];
__device__ float g_bnsum[HH], g_bnsum2[HH];

// ---------------- mma/ldmatrix helpers ----------
__device__ __forceinline__ void ldsm_x4(unsigned& d0, unsigned& d1, unsigned& d2, unsigned& d3,
                                        unsigned addr) {
    asm volatile("ldmatrix.sync.aligned.m8n8.x4.shared.b16 {%0,%1,%2,%3}, [%4];"
                 : "=r"(d0), "=r"(d1), "=r"(d2), "=r"(d3) : "r"(addr));
}
__device__ __forceinline__ void ldsm_x4_t(unsigned& d0, unsigned& d1, unsigned& d2, unsigned& d3,
                                          unsigned addr) {
    asm volatile("ldmatrix.sync.aligned.m8n8.x4.trans.shared.b16 {%0,%1,%2,%3}, [%4];"
                 : "=r"(d0), "=r"(d1), "=r"(d2), "=r"(d3) : "r"(addr));
}
__device__ __forceinline__ void mma16816(float* c, unsigned a0, unsigned a1, unsigned a2,
                                         unsigned a3, unsigned b0, unsigned b1) {
    asm volatile(
        "mma.sync.aligned.m16n8k16.row.col.f32.f16.f16.f32 "
        "{%0,%1,%2,%3}, {%4,%5,%6,%7}, {%8,%9}, {%0,%1,%2,%3};"
        : "+f"(c[0]), "+f"(c[1]), "+f"(c[2]), "+f"(c[3])
        : "r"(a0), "r"(a1), "r"(a2), "r"(a3), "r"(b0), "r"(b1));
}

// ---------------- rw GEMM (K=20) + zero-init + fp16 weight convert ---------
__global__ void k_rw_zero(const float* __restrict__ A, const float* __restrict__ W,
                          const float* __restrict__ bias, float* __restrict__ out,
                          const float* __restrict__ w0, const float* __restrict__ w1,
                          const float* __restrict__ w2, const float* __restrict__ w3,
                          const float* __restrict__ w4, const float* __restrict__ w5,
                          const float* __restrict__ w6) {
    int gtid = blockIdx.x * 256 + threadIdx.x;
    if (gtid < NN) g_deg[gtid] = 0;
    if (gtid < HH) { g_bnsum[gtid] = 0.f; g_bnsum2[gtid] = 0.f; }
    if (gtid < 4096) {
        g_w16[0 * 4096 + gtid] = __float2half_rn(w0[gtid]);
        g_w16[1 * 4096 + gtid] = __float2half_rn(w1[gtid]);
        g_w16[2 * 4096 + gtid] = __float2half_rn(w2[gtid]);
        g_w16[3 * 4096 + gtid] = __float2half_rn(w3[gtid]);
        g_w16[4 * 4096 + gtid] = __float2half_rn(w4[gtid]);
        g_w16[5 * 4096 + gtid] = __float2half_rn(w5[gtid]);
        g_w16[6 * 4096 + gtid] = __float2half_rn(w6[gtid]);
    }

    __shared__ __align__(16) float in_s[64][PP];
    __shared__ __align__(16) float wt_s[PP][64];
    int tid = threadIdx.x;
    int row0 = blockIdx.x * 64;
    {
        const float4* W4 = (const float4*)W;
        float4* ws4 = (float4*)&wt_s[0][0];
        for (int i = tid; i < PP * 16; i += 256) ws4[i] = W4[i];
    }
    {
        const float4* A4 = (const float4*)A;
        for (int i = tid; i < 64 * 5; i += 256) {
            int r = i / 5, c = i % 5;
            int row = row0 + r;
            float4 v = make_float4(0.f, 0.f, 0.f, 0.f);
            if (row < NN) v = A4[row * 5 + c];
            *(((float4*)in_s[r]) + c) = v;
        }
    }
    __syncthreads();
    int tx = tid & 15, ty = tid >> 4;
    float acc[4][4];
#pragma unroll
    for (int i = 0; i < 4; i++)
#pragma unroll
        for (int j = 0; j < 4; j++) acc[i][j] = 0.f;
#pragma unroll
    for (int k = 0; k < PP; k += 4) {
        float4 a[4], b[4];
#pragma unroll
        for (int i = 0; i < 4; i++) a[i] = *(const float4*)&in_s[ty * 4 + i][k];
#pragma unroll
        for (int kk = 0; kk < 4; kk++) b[kk] = *(const float4*)&wt_s[k + kk][tx * 4];
#pragma unroll
        for (int i = 0; i < 4; i++) {
            acc[i][0] += a[i].x * b[0].x + a[i].y * b[1].x + a[i].z * b[2].x + a[i].w * b[3].x;
            acc[i][1] += a[i].x * b[0].y + a[i].y * b[1].y + a[i].z * b[2].y + a[i].w * b[3].y;
            acc[i][2] += a[i].x * b[0].z + a[i].y * b[1].z + a[i].z * b[2].z + a[i].w * b[3].z;
            acc[i][3] += a[i].x * b[0].w + a[i].y * b[1].w + a[i].z * b[2].w + a[i].w * b[3].w;
        }
    }
#pragma unroll
    for (int i = 0; i < 4; i++) {
        int row = row0 + ty * 4 + i;
        if (row >= NN) continue;
        float4 o;
        o.x = acc[i][0] + bias[tx * 4 + 0];
        o.y = acc[i][1] + bias[tx * 4 + 1];
        o.z = acc[i][2] + bias[tx * 4 + 2];
        o.w = acc[i][3] + bias[tx * 4 + 3];
        *(float4*)&out[row * 64 + tx * 4] = o;
    }
}

__global__ void k_deg(const int* __restrict__ dst) {
    int i = blockIdx.x * blockDim.x + threadIdx.x;
    if (i < EE) atomicAdd(&g_deg[dst[i]], 1);
}

__global__ void k_scan_part() {
    int t = threadIdx.x;
    int i = blockIdx.x * 1024 + t;
    int v = (i < NN) ? g_deg[i] : 0;
    if (i < NN) g_dinv[i] = rsqrtf((float)v + 1.0f);
    int r = v;
#pragma unroll
    for (int o = 16; o; o >>= 1) r += __shfl_down_sync(0xffffffffu, r, o);
    __shared__ int ws[32];
    if ((t & 31) == 0) ws[t >> 5] = r;
    __syncthreads();
    if (t < 32) {
        int x = ws[t];
#pragma unroll
        for (int o = 16; o; o >>= 1) x += __shfl_down_sync(0xffffffffu, x, o);
        if (t == 0) g_bsum[blockIdx.x] = x;
    }
}

__global__ void k_scan_final() {
    __shared__ int bs[64];
    __shared__ int wsum[32];
    int t = threadIdx.x;
    if (t < 64) bs[t] = (t < 49) ? g_bsum[t] : 0;
    int i = blockIdx.x * 1024 + t;
    int v = (i < NN) ? g_deg[i] : 0;
    int lane = t & 31, w = t >> 5;
    int incl = v;
#pragma unroll
    for (int o = 1; o < 32; o <<= 1) {
        int x = __shfl_up_sync(0xffffffffu, incl, o);
        if (lane >= o) incl += x;
    }
    if (lane == 31) wsum[w] = incl;
    __syncthreads();
    if (t == 0) {
        int run = 0;
        for (int k = 0; k < 49; k++) { int b = bs[k]; bs[k] = run; run += b; }
    }
    if (t < 32) {
        int x = wsum[t];
        int inc = x;
#pragma unroll
        for (int o = 1; o < 32; o <<= 1) {
            int y = __shfl_up_sync(0xffffffffu, inc, o);
            if (t >= o) inc += y;
        }
        wsum[t] = inc - x;
    }
    __syncthreads();
    int excl = incl - v + wsum[w] + bs[blockIdx.x];
    if (i < NN) {
        g_offs[i] = excl;
        g_cursor[i] = excl;
        if (i == NN - 1) g_offs[NN] = excl + v;
    }
}

__global__ void k_scatter(const int* __restrict__ src, const int* __restrict__ dst) {
    int i = blockIdx.x * blockDim.x + threadIdx.x;
    if (i >= EE) return;
    int d = dst[i];
    int pos = atomicAdd(&g_cursor[d], 1);
    g_csr[pos] = src[i];
}

// ---------------- layer-1 dual GEMM (fp32 inputs x+pe0, pe0) ---------------
__global__ void __launch_bounds__(256) k_dualgemm(
        const float* __restrict__ A0, const float* __restrict__ A20,
        const float* __restrict__ W0, __half2* __restrict__ outH,
        const float* __restrict__ A1, const float* __restrict__ W1,
        __half2* __restrict__ outP) {
    __shared__ __align__(16) __half a_s[128][72];
    __shared__ __align__(16) __half b_s[64][72];
    int tid = threadIdx.x;
    int part = (blockIdx.x >= NB) ? 1 : 0;
    int bx = blockIdx.x - part * NB;
    int row0 = bx * 128;

    const float* A  = part ? A1 : A0;
    const float* A2 = part ? nullptr : A20;
    const float* W  = part ? W1 : W0;
    __half2* out    = part ? outP : outH;

    {
        const float4* W4 = (const float4*)W;
        for (int i = tid; i < 64 * 16; i += 256) {
            int k = i >> 4, c4 = i & 15;
            float4 v = W4[i];
            *(__half2*)&b_s[k][c4 * 4]     = __floats2half2_rn(v.x, v.y);
            *(__half2*)&b_s[k][c4 * 4 + 2] = __floats2half2_rn(v.z, v.w);
        }
    }
    {
        const float4* A4  = (const float4*)A;
        const float4* A24 = (const float4*)A2;
        for (int i = tid; i < 128 * 16; i += 256) {
            int r = i >> 4, c4 = i & 15;
            int row = row0 + r;
            float4 v = make_float4(0.f, 0.f, 0.f, 0.f);
            if (row < NN) {
                v = A4[row * 16 + c4];
                if (!part) {
                    float4 w = A24[row * 16 + c4];
                    v.x += w.x; v.y += w.y; v.z += w.z; v.w += w.w;
                }
            }
            *(__half2*)&a_s[r][c4 * 4]     = __floats2half2_rn(v.x, v.y);
            *(__half2*)&a_s[r][c4 * 4 + 2] = __floats2half2_rn(v.z, v.w);
        }
    }
    __syncthreads();

    int wid = tid >> 5, lane = tid & 31;
    int wr0 = wid * 16;
    float acc[8][4];
#pragma unroll
    for (int n = 0; n < 8; n++)
#pragma unroll
        for (int j = 0; j < 4; j++) acc[n][j] = 0.f;

    unsigned a_base = (unsigned)__cvta_generic_to_shared(&a_s[0][0]);
    unsigned b_base = (unsigned)__cvta_generic_to_shared(&b_s[0][0]);
    unsigned aaddr = a_base + ((wr0 + (lane & 15)) * 72 + ((lane >> 4) * 8)) * 2;
    unsigned baddr = b_base + (((lane & 15)) * 72 + ((lane >> 4) * 8)) * 2;

#pragma unroll
    for (int ks = 0; ks < 4; ks++) {
        unsigned a0, a1, a2, a3;
        ldsm_x4(a0, a1, a2, a3, aaddr + (ks * 16 * 2));
#pragma unroll
        for (int g = 0; g < 4; g++) {
            unsigned b0, b1, b2, b3;
            ldsm_x4_t(b0, b1, b2, b3, baddr + ((ks * 16 * 72 + g * 16) * 2));
            mma16816(acc[2 * g],     a0, a1, a2, a3, b0, b1);
            mma16816(acc[2 * g + 1], a0, a1, a2, a3, b2, b3);
        }
    }

    int r_lo = row0 + wr0 + (lane >> 2);
    int r_hi = r_lo + 8;
    int cq = lane & 3;
    float s_lo = (r_lo < NN) ? g_dinv[r_lo] : 0.f;
    float s_hi = (r_hi < NN) ? g_dinv[r_hi] : 0.f;
#pragma unroll
    for (int nt = 0; nt < 8; nt++) {
        if (r_lo < NN)
            out[r_lo * 32 + nt * 4 + cq] = __floats2half2_rn(acc[nt][0] * s_lo, acc[nt][1] * s_lo);
        if (r_hi < NN)
            out[r_hi * 32 + nt * 4 + cq] = __floats2half2_rn(acc[nt][2] * s_hi, acc[nt][3] * s_hi);
    }
}

// ---------------- layers 2-5 dual GEMM, fp16 A + fp16 W --------------------
template <bool DUAL>
__global__ void __launch_bounds__(256) k_dualgemm16(
        const __half2* __restrict__ hp, const __half* __restrict__ Wh0,
        __half2* __restrict__ outH,
        const __half2* __restrict__ pe16, const __half* __restrict__ Wh1,
        __half2* __restrict__ outP) {
    __shared__ __align__(16) __half a_s[128][72];
    __shared__ __align__(16) __half b_s[64][72];
    int tid = threadIdx.x;
    int part = DUAL ? ((blockIdx.x >= NB) ? 1 : 0) : 0;
    int bx = blockIdx.x - part * NB;
    int row0 = bx * 128;

    const __half2* A = part ? pe16 : hp;
    const __half* Wh = part ? Wh1 : Wh0;
    __half2* out     = part ? outP : outH;

    {
        const uint4* W4 = (const uint4*)Wh;          // 64 rows x 8 uint4
        for (int i = tid; i < 512; i += 256) {
            int k = i >> 3, c8 = i & 7;
            *(uint4*)&b_s[k][c8 * 8] = W4[i];
        }
    }
    {
        const uint4* A4 = (const uint4*)A;
        for (int i = tid; i < 128 * 8; i += 256) {
            int r = i >> 3, c8 = i & 7;
            int row = row0 + r;
            uint4 v = make_uint4(0u, 0u, 0u, 0u);
            if (row < NN) v = A4[row * 8 + c8];
            *(uint4*)&a_s[r][c8 * 8] = v;
        }
    }
    __syncthreads();

    int wid = tid >> 5, lane = tid & 31;
    int wr0 = wid * 16;
    float acc[8][4];
#pragma unroll
    for (int n = 0; n < 8; n++)
#pragma unroll
        for (int j = 0; j < 4; j++) acc[n][j] = 0.f;

    unsigned a_base = (unsigned)__cvta_generic_to_shared(&a_s[0][0]);
    unsigned b_base = (unsigned)__cvta_generic_to_shared(&b_s[0][0]);
    unsigned aaddr = a_base + ((wr0 + (lane & 15)) * 72 + ((lane >> 4) * 8)) * 2;
    unsigned baddr = b_base + (((lane & 15)) * 72 + ((lane >> 4) * 8)) * 2;

#pragma unroll
    for (int ks = 0; ks < 4; ks++) {
        unsigned a0, a1, a2, a3;
        ldsm_x4(a0, a1, a2, a3, aaddr + (ks * 16 * 2));
#pragma unroll
        for (int g = 0; g < 4; g++) {
            unsigned b0, b1, b2, b3;
            ldsm_x4_t(b0, b1, b2, b3, baddr + ((ks * 16 * 72 + g * 16) * 2));
            mma16816(acc[2 * g],     a0, a1, a2, a3, b0, b1);
            mma16816(acc[2 * g + 1], a0, a1, a2, a3, b2, b3);
        }
    }

    int r_lo = row0 + wr0 + (lane >> 2);
    int r_hi = r_lo + 8;
    int cq = lane & 3;
    float s_lo = (r_lo < NN) ? g_dinv[r_lo] : 0.f;
    float s_hi = (r_hi < NN) ? g_dinv[r_hi] : 0.f;
#pragma unroll
    for (int nt = 0; nt < 8; nt++) {
        if (r_lo < NN)
            out[r_lo * 32 + nt * 4 + cq] = __floats2half2_rn(acc[nt][0] * s_lo, acc[nt][1] * s_lo);
        if (r_hi < NN)
            out[r_hi * 32 + nt * 4 + cq] = __floats2half2_rn(acc[nt][2] * s_hi, acc[nt][3] * s_hi);
    }
}

// ---------------- dual aggregation -> hp fp16, pe fp16 (4-edge unroll) -----
__global__ void k_aggr2(const __half2* __restrict__ tH, const __half2* __restrict__ tP,
                        const float* __restrict__ bc, const float* __restrict__ bp,
                        __half2* __restrict__ hp, __half2* __restrict__ pe16) {
    int wid = (blockIdx.x * blockDim.x + threadIdx.x) >> 5;
    int lane = threadIdx.x & 31;
    if (wid >= NN) return;
    int beg = g_offs[wid], end = g_offs[wid + 1];

    float2 aH = __half22float2(__ldg(&tH[wid * 32 + lane]));  // self (already *dinv)
    float2 aP = __half22float2(__ldg(&tP[wid * 32 + lane]));

    int e = beg;
    for (; e + 4 <= end; e += 4) {
        int s0 = g_csr[e], s1 = g_csr[e + 1], s2 = g_csr[e + 2], s3 = g_csr[e + 3];
        __half2 h0 = __ldg(&tH[s0 * 32 + lane]);
        __half2 h1 = __ldg(&tH[s1 * 32 + lane]);
        __half2 h2 = __ldg(&tH[s2 * 32 + lane]);
        __half2 h3 = __ldg(&tH[s3 * 32 + lane]);
        __half2 p0 = __ldg(&tP[s0 * 32 + lane]);
        __half2 p1 = __ldg(&tP[s1 * 32 + lane]);
        __half2 p2 = __ldg(&tP[s2 * 32 + lane]);
        __half2 p3 = __ldg(&tP[s3 * 32 + lane]);
        float2 f0 = __half22float2(h0), f1 = __half22float2(h1);
        float2 f2 = __half22float2(h2), f3 = __half22float2(h3);
        aH.x += (f0.x + f1.x) + (f2.x + f3.x);
        aH.y += (f0.y + f1.y) + (f2.y + f3.y);
        float2 g0 = __half22float2(p0), g1 = __half22float2(p1);
        float2 g2 = __half22float2(p2), g3 = __half22float2(p3);
        aP.x += (g0.x + g1.x) + (g2.x + g3.x);
        aP.y += (g0.y + g1.y) + (g2.y + g3.y);
    }
    for (; e < end; e++) {
        int s = g_csr[e];
        float2 f = __half22float2(__ldg(&tH[s * 32 + lane]));
        float2 g = __half22float2(__ldg(&tP[s * 32 + lane]));
        aH.x += f.x; aH.y += f.y;
        aP.x += g.x; aP.y += g.y;
    }

    float d = g_dinv[wid];
    float2 bcl = ((const float2*)bc)[lane];
    float2 bpl = ((const float2*)bp)[lane];
    float hx = fmaxf(aH.x * d + bcl.x, 0.f);
    float hy = fmaxf(aH.y * d + bcl.y, 0.f);
    float px = fmaxf(aP.x * d + bpl.x, 0.f);
    float py = fmaxf(aP.y * d + bpl.y, 0.f);
    hp[wid * 32 + lane]   = __floats2half2_rn(hx + px, hy + py);
    pe16[wid * 32 + lane] = __floats2half2_rn(px, py);
}

// ---------------- final aggregation + fused BN statistics ------------------
// NOTE: AGB*8 == NN exactly, so every warp has a valid node (no early return).
__global__ void k_aggr_final(const __half2* __restrict__ tH, const float* __restrict__ bc,
                             float* __restrict__ h) {
    int wid = (blockIdx.x * blockDim.x + threadIdx.x) >> 5;
    int lane = threadIdx.x & 31;
    int lw = threadIdx.x >> 5;
    int beg = g_offs[wid], end = g_offs[wid + 1];
    float2 aH = __half22float2(__ldg(&tH[wid * 32 + lane]));
    int e = beg;
    for (; e + 4 <= end; e += 4) {
        int s0 = g_csr[e], s1 = g_csr[e + 1], s2 = g_csr[e + 2], s3 = g_csr[e + 3];
        float2 f0 = __half22float2(__ldg(&tH[s0 * 32 + lane]));
        float2 f1 = __half22float2(__ldg(&tH[s1 * 32 + lane]));
        float2 f2 = __half22float2(__ldg(&tH[s2 * 32 + lane]));
        float2 f3 = __half22float2(__ldg(&tH[s3 * 32 + lane]));
        aH.x += (f0.x + f1.x) + (f2.x + f3.x);
        aH.y += (f0.y + f1.y) + (f2.y + f3.y);
    }
    for (; e < end; e++) {
        int s = g_csr[e];
        float2 f = __half22float2(__ldg(&tH[s * 32 + lane]));
        aH.x += f.x; aH.y += f.y;
    }
    float d = g_dinv[wid];
    float2 bv = ((const float2*)bc)[lane];
    float ox = aH.x * d + bv.x;
    float oy = aH.y * d + bv.y;
    ((float2*)h)[wid * 32 + lane] = make_float2(ox, oy);

    // block reduce BN sums (8 nodes x 64 cols) -> atomics
    __shared__ float ssx[8][32], ssy[8][32], sqx[8][32], sqy[8][32];
    ssx[lw][lane] = ox; ssy[lw][lane] = oy;
    sqx[lw][lane] = ox * ox; sqy[lw][lane] = oy * oy;
    __syncthreads();
    if (threadIdx.x < 32) {
        int t = threadIdx.x;
        float sx = 0.f, sy = 0.f, qx = 0.f, qy = 0.f;
#pragma unroll
        for (int r = 0; r < 8; r++) {
            sx += ssx[r][t]; sy += ssy[r][t];
            qx += sqx[r][t]; qy += sqy[r][t];
        }
        atomicAdd(&g_bnsum[2 * t], sx);
        atomicAdd(&g_bnsum[2 * t + 1], sy);
        atomicAdd(&g_bnsum2[2 * t], qx);
        atomicAdd(&g_bnsum2[2 * t + 1], qy);
    }
}

// ---------------- fused norm/relu/pool -------------------------------------
__global__ void k_pool(const float* __restrict__ h, const int* __restrict__ ptr,
                       const float* __restrict__ gamma, const float* __restrict__ beta,
                       float* __restrict__ out) {
    __shared__ float sscale[64], sshift[64];
    int t = threadIdx.x;
    if (t < 64) {
        float mu = g_bnsum[t] / (float)NN;
        float var = g_bnsum2[t] / (float)NN - mu * mu;
        float r = rsqrtf(var + 1e-5f);
        float sc = r * gamma[t];
        sscale[t] = sc;
        sshift[t] = beta[t] - mu * sc;
    }
    __syncthreads();
    int g = blockIdx.x;
    int beg = ptr[g], end = ptr[g + 1];
    int col = t & 63, sub = t >> 6;
    float acc = 0.f;
    for (int r = beg + sub; r < end; r += 4) {
        float v = h[r * 64 + col] * sscale[col] + sshift[col];
        acc += fmaxf(v, 0.f);
    }
    __shared__ float sh[4][64];
    sh[sub][col] = acc;
    __syncthreads();
    if (sub == 0) {
        float s = sh[0][col] + sh[1][col] + sh[2][col] + sh[3][col];
        out[g * 64 + col] = s / (float)(end - beg);
    }
}

// ---------------- launch ----------------------------------------------------
extern "C" void kernel_launch(void* const* d_in, const int* in_sizes, int n_in,
                              void* d_out, int out_size) {
    const float* x     = (const float*)d_in[0];
    const float* rwpe  = (const float*)d_in[1];
    const float* W_rw  = (const float*)d_in[2];
    const float* b_rw  = (const float*)d_in[3];
    const float *Wc[5], *bc[5], *Wp[5], *bp[5];
    for (int i = 0; i < 5; i++) {
        Wc[i] = (const float*)d_in[4 + 4 * i];
        bc[i] = (const float*)d_in[5 + 4 * i];
        Wp[i] = (const float*)d_in[6 + 4 * i];
        bp[i] = (const float*)d_in[7 + 4 * i];
    }
    const float* gamma = (const float*)d_in[24];
    const float* beta  = (const float*)d_in[25];
    const int*   ei    = (const int*)d_in[26];
    const int*   ptr   = (const int*)d_in[27];
    float*       out   = (float*)d_out;
    const int* src = ei;
    const int* dst = ei + EE;

    float *pe, *h;
    __half2 *tH, *tP, *hp, *pe16;
    __half* wh;
    cudaGetSymbolAddress((void**)&pe, g_pe);
    cudaGetSymbolAddress((void**)&h, g_h);
    cudaGetSymbolAddress((void**)&tH, g_tH);
    cudaGetSymbolAddress((void**)&tP, g_tP);
    cudaGetSymbolAddress((void**)&hp, g_hp);
    cudaGetSymbolAddress((void**)&pe16, g_pe16);
    cudaGetSymbolAddress((void**)&wh, g_w16);

    // single stream, R11 ordering:
    // rw+zero+w16(1) -> deg(2) -> scan_part+dinv(3) -> gemm1(4, PROFILED)
    // -> scan_final(5) -> scatter(6) -> [aggr2 -> gemm16] x4 -> final -> pool
    k_rw_zero<<<(NN + 63) / 64, 256>>>(rwpe, W_rw, b_rw, pe,
                                       Wc[1], Wc[2], Wc[3], Wc[4],
                                       Wp[1], Wp[2], Wp[3]);         // 1
    k_deg<<<(EE + 255) / 256, 256>>>(dst);                           // 2
    k_scan_part<<<49, 1024>>>();                                     // 3 (dinv)
    k_dualgemm<<<2 * NB, 256>>>(x, pe, Wc[0], tH, pe, Wp[0], tP);    // 4 (profiled)
    k_scan_final<<<49, 1024>>>();                                    // 5
    k_scatter<<<(EE + 255) / 256, 256>>>(src, dst);                  // 6

    for (int k = 0; k < 3; k++) {
        k_aggr2<<<AGB, 256>>>(tH, tP, bc[k], bp[k], hp, pe16);
        k_dualgemm16<true><<<2 * NB, 256>>>(hp, wh + k * 4096, tH,
                                            pe16, wh + (4 + k) * 4096, tP);
    }
    k_aggr2<<<AGB, 256>>>(tH, tP, bc[3], bp[3], hp, pe16);
    k_dualgemm16<false><<<NB, 256>>>(hp, wh + 3 * 4096, tH, nullptr, nullptr, nullptr);
    k_aggr_final<<<AGB, 256>>>(tH, bc[4], h);        // + fused BN stats

    k_pool<<<GG, 256>>>(h, ptr, gamma, beta, out);
}

// round 17
// speedup vs baseline: 1.1185x; 1.1185x over previous
#include <cuda_runtime.h>
#include <cuda_fp16.h>

#define NN 50000
#define EE 800000
#define HH 64
#define PP 20
#define GG 500
#define NB 391           // (NN+127)/128 gemm tiles
#define AGB 6250         // NN warps / 8 per block

// ---------------- device scratch ----------
__device__ float g_h[NN * HH];                        // conv5 output (BN/pool input)
__device__ __align__(16) __half2 g_tH[NN * 32];       // messages H
__device__ __align__(16) __half2 g_tP[NN * 32];       // messages P
__device__ __align__(16) __half2 g_hp[NN * 32];       // h+pe fp16 (gemm A part0)
__device__ __align__(16) __half2 g_pe16[NN * 32];     // pe fp16  (gemm A part1)
__device__ float g_dinv[NN];
__device__ int   g_deg[NN];
__device__ int   g_offs[NN + 1];
__device__ int   g_cursor[NN];
__device__ int   g_csr[EE];
__device__ int   g_bsum[64];
__device__ float g_bnsum[HH], g_bnsum2[HH];

// ---------------- mma/ldmatrix helpers ----------
__device__ __forceinline__ void ldsm_x4(unsigned& d0, unsigned& d1, unsigned& d2, unsigned& d3,
                                        unsigned addr) {
    asm volatile("ldmatrix.sync.aligned.m8n8.x4.shared.b16 {%0,%1,%2,%3}, [%4];"
                 : "=r"(d0), "=r"(d1), "=r"(d2), "=r"(d3) : "r"(addr));
}
__device__ __forceinline__ void ldsm_x4_t(unsigned& d0, unsigned& d1, unsigned& d2, unsigned& d3,
                                          unsigned addr) {
    asm volatile("ldmatrix.sync.aligned.m8n8.x4.trans.shared.b16 {%0,%1,%2,%3}, [%4];"
                 : "=r"(d0), "=r"(d1), "=r"(d2), "=r"(d3) : "r"(addr));
}
__device__ __forceinline__ void mma16816(float* c, unsigned a0, unsigned a1, unsigned a2,
                                         unsigned a3, unsigned b0, unsigned b1) {
    asm volatile(
        "mma.sync.aligned.m16n8k16.row.col.f32.f16.f16.f32 "
        "{%0,%1,%2,%3}, {%4,%5,%6,%7}, {%8,%9}, {%0,%1,%2,%3};"
        : "+f"(c[0]), "+f"(c[1]), "+f"(c[2]), "+f"(c[3])
        : "r"(a0), "r"(a1), "r"(a2), "r"(a3), "r"(b0), "r"(b1));
}

// ---------------- zero accumulators ----------------------------------------
__global__ void k_zero() {
    int i = blockIdx.x * blockDim.x + threadIdx.x;
    if (i < NN) g_deg[i] = 0;
    if (i < HH) { g_bnsum[i] = 0.f; g_bnsum2[i] = 0.f; }
}

__global__ void k_deg(const int* __restrict__ dst) {
    int i = blockIdx.x * blockDim.x + threadIdx.x;
    if (i < EE) atomicAdd(&g_deg[dst[i]], 1);
}

__global__ void k_scan_part() {
    int t = threadIdx.x;
    int i = blockIdx.x * 1024 + t;
    int v = (i < NN) ? g_deg[i] : 0;
    if (i < NN) g_dinv[i] = rsqrtf((float)v + 1.0f);
    int r = v;
#pragma unroll
    for (int o = 16; o; o >>= 1) r += __shfl_down_sync(0xffffffffu, r, o);
    __shared__ int ws[32];
    if ((t & 31) == 0) ws[t >> 5] = r;
    __syncthreads();
    if (t < 32) {
        int x = ws[t];
#pragma unroll
        for (int o = 16; o; o >>= 1) x += __shfl_down_sync(0xffffffffu, x, o);
        if (t == 0) g_bsum[blockIdx.x] = x;
    }
}

__global__ void k_scan_final() {
    __shared__ int bs[64];
    __shared__ int wsum[32];
    int t = threadIdx.x;
    if (t < 64) bs[t] = (t < 49) ? g_bsum[t] : 0;
    int i = blockIdx.x * 1024 + t;
    int v = (i < NN) ? g_deg[i] : 0;
    int lane = t & 31, w = t >> 5;
    int incl = v;
#pragma unroll
    for (int o = 1; o < 32; o <<= 1) {
        int x = __shfl_up_sync(0xffffffffu, incl, o);
        if (lane >= o) incl += x;
    }
    if (lane == 31) wsum[w] = incl;
    __syncthreads();
    if (t == 0) {
        int run = 0;
        for (int k = 0; k < 49; k++) { int b = bs[k]; bs[k] = run; run += b; }
    }
    if (t < 32) {
        int x = wsum[t];
        int inc = x;
#pragma unroll
        for (int o = 1; o < 32; o <<= 1) {
            int y = __shfl_up_sync(0xffffffffu, inc, o);
            if (t >= o) inc += y;
        }
        wsum[t] = inc - x;
    }
    __syncthreads();
    int excl = incl - v + wsum[w] + bs[blockIdx.x];
    if (i < NN) {
        g_offs[i] = excl;
        g_cursor[i] = excl;
        if (i == NN - 1) g_offs[NN] = excl + v;
    }
}

__global__ void k_scatter(const int* __restrict__ src, const int* __restrict__ dst) {
    int i = blockIdx.x * blockDim.x + threadIdx.x;
    if (i >= EE) return;
    int d = dst[i];
    int pos = atomicAdd(&g_cursor[d], 1);
    g_csr[pos] = src[i];
}

// ---------------- fused layer-1 GEMM: pe computed in-block -----------------
// part0: (x + (RWPE@Wrw + brw)) @ Wc1 * dinv -> outH
// part1: (RWPE@Wrw + brw)       @ Wp1 * dinv -> outP
// pe via HMMA (K padded 20->32); no pe0 buffer ever touches gmem.
__global__ void __launch_bounds__(256) k_gemm1(
        const float* __restrict__ x, const float* __restrict__ rwpe,
        const float* __restrict__ Wrw, const float* __restrict__ brw,
        const float* __restrict__ Wc1, __half2* __restrict__ outH,
        const float* __restrict__ Wp1, __half2* __restrict__ outP) {
    __shared__ __align__(16) __half arw_s[128][40];   // RWPE, K padded to 32, stride 40
    __shared__ __align__(16) __half brw_s[32][72];    // Wrw padded to 32 rows
    __shared__ __align__(16) __half a_s[128][72];     // main A tile
    __shared__ __align__(16) __half b_s[64][72];      // main W tile
    int tid = threadIdx.x;
    int part = (blockIdx.x >= NB) ? 1 : 0;
    int bx = blockIdx.x - part * NB;
    int row0 = bx * 128;

    const float* W = part ? Wp1 : Wc1;
    __half2* out   = part ? outP : outH;

    // stage main W fp32 -> fp16
    {
        const float4* W4 = (const float4*)W;
        for (int i = tid; i < 64 * 16; i += 256) {
            int k = i >> 4, c4 = i & 15;
            float4 v = W4[i];
            *(__half2*)&b_s[k][c4 * 4]     = __floats2half2_rn(v.x, v.y);
            *(__half2*)&b_s[k][c4 * 4 + 2] = __floats2half2_rn(v.z, v.w);
        }
    }
    // stage Wrw padded (rows 20..31 zero)
    for (int i = tid; i < 32 * 64; i += 256) {
        int k = i >> 6, c = i & 63;
        brw_s[k][c] = __float2half_rn((k < PP) ? Wrw[k * 64 + c] : 0.f);
    }
    // stage RWPE padded (cols 20..31 zero)
    for (int i = tid; i < 128 * 32; i += 256) {
        int r = i >> 5, k = i & 31;
        int row = row0 + r;
        float v = (row < NN && k < PP) ? rwpe[row * PP + k] : 0.f;
        arw_s[r][k] = __float2half_rn(v);
    }
    __syncthreads();

    int wid = tid >> 5, lane = tid & 31;
    int wr0 = wid * 16;

    // ---- MMA1: pe = RWPE @ Wrw (2 k-steps) ----
    float pacc[8][4];
#pragma unroll
    for (int n = 0; n < 8; n++)
#pragma unroll
        for (int j = 0; j < 4; j++) pacc[n][j] = 0.f;
    {
        unsigned a1b = (unsigned)__cvta_generic_to_shared(&arw_s[0][0]);
        unsigned b1b = (unsigned)__cvta_generic_to_shared(&brw_s[0][0]);
        unsigned aaddr = a1b + ((wr0 + (lane & 15)) * 40 + ((lane >> 4) * 8)) * 2;
        unsigned baddr = b1b + (((lane & 15)) * 72 + ((lane >> 4) * 8)) * 2;
#pragma unroll
        for (int ks = 0; ks < 2; ks++) {
            unsigned a0, a1, a2, a3;
            ldsm_x4(a0, a1, a2, a3, aaddr + (ks * 16 * 2));
#pragma unroll
            for (int g = 0; g < 4; g++) {
                unsigned b0, b1, b2, b3;
                ldsm_x4_t(b0, b1, b2, b3, baddr + ((ks * 16 * 72 + g * 16) * 2));
                mma16816(pacc[2 * g],     a0, a1, a2, a3, b0, b1);
                mma16816(pacc[2 * g + 1], a0, a1, a2, a3, b2, b3);
            }
        }
    }

    // ---- build main A tile from pe fragment (+ x for part0) ----
    {
        int rl = wr0 + (lane >> 2);     // local rows
        int rh = rl + 8;
        int grl = row0 + rl, grh = row0 + rh;
#pragma unroll
        for (int nt = 0; nt < 8; nt++) {
            int col = nt * 8 + (lane & 3) * 2;
            float2 bb = *(const float2*)&brw[col];
            float p0 = pacc[nt][0] + bb.x, p1 = pacc[nt][1] + bb.y;
            float p2 = pacc[nt][2] + bb.x, p3 = pacc[nt][3] + bb.y;
            if (!part) {
                if (grl < NN) {
                    float2 xv = *(const float2*)&x[grl * 64 + col];
                    p0 += xv.x; p1 += xv.y;
                }
                if (grh < NN) {
                    float2 xv = *(const float2*)&x[grh * 64 + col];
                    p2 += xv.x; p3 += xv.y;
                }
            }
            if (grl >= NN) { p0 = 0.f; p1 = 0.f; }
            if (grh >= NN) { p2 = 0.f; p3 = 0.f; }
            *(__half2*)&a_s[rl][col] = __floats2half2_rn(p0, p1);
            *(__half2*)&a_s[rh][col] = __floats2half2_rn(p2, p3);
        }
    }
    __syncthreads();

    // ---- main MMA (as R11) ----
    float acc[8][4];
#pragma unroll
    for (int n = 0; n < 8; n++)
#pragma unroll
        for (int j = 0; j < 4; j++) acc[n][j] = 0.f;

    unsigned a_base = (unsigned)__cvta_generic_to_shared(&a_s[0][0]);
    unsigned b_base = (unsigned)__cvta_generic_to_shared(&b_s[0][0]);
    unsigned aaddr = a_base + ((wr0 + (lane & 15)) * 72 + ((lane >> 4) * 8)) * 2;
    unsigned baddr = b_base + (((lane & 15)) * 72 + ((lane >> 4) * 8)) * 2;

#pragma unroll
    for (int ks = 0; ks < 4; ks++) {
        unsigned a0, a1, a2, a3;
        ldsm_x4(a0, a1, a2, a3, aaddr + (ks * 16 * 2));
#pragma unroll
        for (int g = 0; g < 4; g++) {
            unsigned b0, b1, b2, b3;
            ldsm_x4_t(b0, b1, b2, b3, baddr + ((ks * 16 * 72 + g * 16) * 2));
            mma16816(acc[2 * g],     a0, a1, a2, a3, b0, b1);
            mma16816(acc[2 * g + 1], a0, a1, a2, a3, b2, b3);
        }
    }

    int r_lo = row0 + wr0 + (lane >> 2);
    int r_hi = r_lo + 8;
    int cq = lane & 3;
    float s_lo = (r_lo < NN) ? g_dinv[r_lo] : 0.f;
    float s_hi = (r_hi < NN) ? g_dinv[r_hi] : 0.f;
#pragma unroll
    for (int nt = 0; nt < 8; nt++) {
        if (r_lo < NN)
            out[r_lo * 32 + nt * 4 + cq] = __floats2half2_rn(acc[nt][0] * s_lo, acc[nt][1] * s_lo);
        if (r_hi < NN)
            out[r_hi * 32 + nt * 4 + cq] = __floats2half2_rn(acc[nt][2] * s_hi, acc[nt][3] * s_hi);
    }
}

// ---------------- layers 2-5 dual GEMM, fp16 A, fp32 W (R11 version) -------
template <bool DUAL>
__global__ void __launch_bounds__(256) k_dualgemm16(
        const __half2* __restrict__ hp, const float* __restrict__ W0,
        __half2* __restrict__ outH,
        const __half2* __restrict__ pe16, const float* __restrict__ W1,
        __half2* __restrict__ outP) {
    __shared__ __align__(16) __half a_s[128][72];
    __shared__ __align__(16) __half b_s[64][72];
    int tid = threadIdx.x;
    int part = DUAL ? ((blockIdx.x >= NB) ? 1 : 0) : 0;
    int bx = blockIdx.x - part * NB;
    int row0 = bx * 128;

    const __half2* A = part ? pe16 : hp;
    const float* W   = part ? W1 : W0;
    __half2* out     = part ? outP : outH;

    {
        const float4* W4 = (const float4*)W;
        for (int i = tid; i < 64 * 16; i += 256) {
            int k = i >> 4, c4 = i & 15;
            float4 v = W4[i];
            *(__half2*)&b_s[k][c4 * 4]     = __floats2half2_rn(v.x, v.y);
            *(__half2*)&b_s[k][c4 * 4 + 2] = __floats2half2_rn(v.z, v.w);
        }
    }
    {
        const uint4* A4 = (const uint4*)A;
        for (int i = tid; i < 128 * 8; i += 256) {
            int r = i >> 3, c8 = i & 7;
            int row = row0 + r;
            uint4 v = make_uint4(0u, 0u, 0u, 0u);
            if (row < NN) v = A4[row * 8 + c8];
            *(uint4*)&a_s[r][c8 * 8] = v;
        }
    }
    __syncthreads();

    int wid = tid >> 5, lane = tid & 31;
    int wr0 = wid * 16;
    float acc[8][4];
#pragma unroll
    for (int n = 0; n < 8; n++)
#pragma unroll
        for (int j = 0; j < 4; j++) acc[n][j] = 0.f;

    unsigned a_base = (unsigned)__cvta_generic_to_shared(&a_s[0][0]);
    unsigned b_base = (unsigned)__cvta_generic_to_shared(&b_s[0][0]);
    unsigned aaddr = a_base + ((wr0 + (lane & 15)) * 72 + ((lane >> 4) * 8)) * 2;
    unsigned baddr = b_base + (((lane & 15)) * 72 + ((lane >> 4) * 8)) * 2;

#pragma unroll
    for (int ks = 0; ks < 4; ks++) {
        unsigned a0, a1, a2, a3;
        ldsm_x4(a0, a1, a2, a3, aaddr + (ks * 16 * 2));
#pragma unroll
        for (int g = 0; g < 4; g++) {
            unsigned b0, b1, b2, b3;
            ldsm_x4_t(b0, b1, b2, b3, baddr + ((ks * 16 * 72 + g * 16) * 2));
            mma16816(acc[2 * g],     a0, a1, a2, a3, b0, b1);
            mma16816(acc[2 * g + 1], a0, a1, a2, a3, b2, b3);
        }
    }

    int r_lo = row0 + wr0 + (lane >> 2);
    int r_hi = r_lo + 8;
    int cq = lane & 3;
    float s_lo = (r_lo < NN) ? g_dinv[r_lo] : 0.f;
    float s_hi = (r_hi < NN) ? g_dinv[r_hi] : 0.f;
#pragma unroll
    for (int nt = 0; nt < 8; nt++) {
        if (r_lo < NN)
            out[r_lo * 32 + nt * 4 + cq] = __floats2half2_rn(acc[nt][0] * s_lo, acc[nt][1] * s_lo);
        if (r_hi < NN)
            out[r_hi * 32 + nt * 4 + cq] = __floats2half2_rn(acc[nt][2] * s_hi, acc[nt][3] * s_hi);
    }
}

// ---------------- dual aggregation -> hp fp16, pe fp16 (R11 version) -------
__global__ void k_aggr2(const __half2* __restrict__ tH, const __half2* __restrict__ tP,
                        const float* __restrict__ bc, const float* __restrict__ bp,
                        __half2* __restrict__ hp, __half2* __restrict__ pe16) {
    int wid = (blockIdx.x * blockDim.x + threadIdx.x) >> 5;
    int lane = threadIdx.x & 31;
    if (wid >= NN) return;
    int beg = g_offs[wid], end = g_offs[wid + 1];

    float2 aH = __half22float2(__ldg(&tH[wid * 32 + lane]));  // self (already *dinv)
    float2 aP = __half22float2(__ldg(&tP[wid * 32 + lane]));

    int e = beg;
    for (; e + 4 <= end; e += 4) {
        int s0 = g_csr[e], s1 = g_csr[e + 1], s2 = g_csr[e + 2], s3 = g_csr[e + 3];
        __half2 h0 = __ldg(&tH[s0 * 32 + lane]);
        __half2 h1 = __ldg(&tH[s1 * 32 + lane]);
        __half2 h2 = __ldg(&tH[s2 * 32 + lane]);
        __half2 h3 = __ldg(&tH[s3 * 32 + lane]);
        __half2 p0 = __ldg(&tP[s0 * 32 + lane]);
        __half2 p1 = __ldg(&tP[s1 * 32 + lane]);
        __half2 p2 = __ldg(&tP[s2 * 32 + lane]);
        __half2 p3 = __ldg(&tP[s3 * 32 + lane]);
        float2 f0 = __half22float2(h0), f1 = __half22float2(h1);
        float2 f2 = __half22float2(h2), f3 = __half22float2(h3);
        aH.x += (f0.x + f1.x) + (f2.x + f3.x);
        aH.y += (f0.y + f1.y) + (f2.y + f3.y);
        float2 g0 = __half22float2(p0), g1 = __half22float2(p1);
        float2 g2 = __half22float2(p2), g3 = __half22float2(p3);
        aP.x += (g0.x + g1.x) + (g2.x + g3.x);
        aP.y += (g0.y + g1.y) + (g2.y + g3.y);
    }
    for (; e < end; e++) {
        int s = g_csr[e];
        float2 f = __half22float2(__ldg(&tH[s * 32 + lane]));
        float2 g = __half22float2(__ldg(&tP[s * 32 + lane]));
        aH.x += f.x; aH.y += f.y;
        aP.x += g.x; aP.y += g.y;
    }

    float d = g_dinv[wid];
    float2 bcl = ((const float2*)bc)[lane];
    float2 bpl = ((const float2*)bp)[lane];
    float hx = fmaxf(aH.x * d + bcl.x, 0.f);
    float hy = fmaxf(aH.y * d + bcl.y, 0.f);
    float px = fmaxf(aP.x * d + bpl.x, 0.f);
    float py = fmaxf(aP.y * d + bpl.y, 0.f);
    hp[wid * 32 + lane]   = __floats2half2_rn(hx + px, hy + py);
    pe16[wid * 32 + lane] = __floats2half2_rn(px, py);
}

// ---------------- final aggregation (H only, fp32 out, no relu) ------------
__global__ void k_aggr_final(const __half2* __restrict__ tH, const float* __restrict__ bc,
                             float* __restrict__ h) {
    int wid = (blockIdx.x * blockDim.x + threadIdx.x) >> 5;
    int lane = threadIdx.x & 31;
    if (wid >= NN) return;
    int beg = g_offs[wid], end = g_offs[wid + 1];
    float2 aH = __half22float2(__ldg(&tH[wid * 32 + lane]));
    int e = beg;
    for (; e + 4 <= end; e += 4) {
        int s0 = g_csr[e], s1 = g_csr[e + 1], s2 = g_csr[e + 2], s3 = g_csr[e + 3];
        float2 f0 = __half22float2(__ldg(&tH[s0 * 32 + lane]));
        float2 f1 = __half22float2(__ldg(&tH[s1 * 32 + lane]));
        float2 f2 = __half22float2(__ldg(&tH[s2 * 32 + lane]));
        float2 f3 = __half22float2(__ldg(&tH[s3 * 32 + lane]));
        aH.x += (f0.x + f1.x) + (f2.x + f3.x);
        aH.y += (f0.y + f1.y) + (f2.y + f3.y);
    }
    for (; e < end; e++) {
        int s = g_csr[e];
        float2 f = __half22float2(__ldg(&tH[s * 32 + lane]));
        aH.x += f.x; aH.y += f.y;
    }
    float d = g_dinv[wid];
    float2 bv = ((const float2*)bc)[lane];
    ((float2*)h)[wid * 32 + lane] = make_float2(aH.x * d + bv.x, aH.y * d + bv.y);
}

// ---------------- BatchNorm stats + fused norm/relu/pool -------------------
__global__ void k_bn_stats(const float* __restrict__ h) {
    int t = threadIdx.x;
    int col = t & 63, sub = t >> 6;
    float s = 0.f, s2 = 0.f;
    for (int r = blockIdx.x * 4 + sub; r < NN; r += gridDim.x * 4) {
        float v = h[r * 64 + col];
        s += v; s2 += v * v;
    }
    __shared__ float sh[4][64], sh2[4][64];
    sh[sub][col] = s; sh2[sub][col] = s2;
    __syncthreads();
    if (sub == 0) {
        float ts = sh[0][col] + sh[1][col] + sh[2][col] + sh[3][col];
        float t2 = sh2[0][col] + sh2[1][col] + sh2[2][col] + sh2[3][col];
        atomicAdd(&g_bnsum[col], ts);
        atomicAdd(&g_bnsum2[col], t2);
    }
}

__global__ void k_pool(const float* __restrict__ h, const int* __restrict__ ptr,
                       const float* __restrict__ gamma, const float* __restrict__ beta,
                       float* __restrict__ out) {
    __shared__ float sscale[64], sshift[64];
    int t = threadIdx.x;
    if (t < 64) {
        float mu = g_bnsum[t] / (float)NN;
        float var = g_bnsum2[t] / (float)NN - mu * mu;
        float r = rsqrtf(var + 1e-5f);
        float sc = r * gamma[t];
        sscale[t] = sc;
        sshift[t] = beta[t] - mu * sc;
    }
    __syncthreads();
    int g = blockIdx.x;
    int beg = ptr[g], end = ptr[g + 1];
    int col = t & 63, sub = t >> 6;
    float acc = 0.f;
    for (int r = beg + sub; r < end; r += 4) {
        float v = h[r * 64 + col] * sscale[col] + sshift[col];
        acc += fmaxf(v, 0.f);
    }
    __shared__ float sh[4][64];
    sh[sub][col] = acc;
    __syncthreads();
    if (sub == 0) {
        float s = sh[0][col] + sh[1][col] + sh[2][col] + sh[3][col];
        out[g * 64 + col] = s / (float)(end - beg);
    }
}

// ---------------- launch ----------------------------------------------------
extern "C" void kernel_launch(void* const* d_in, const int* in_sizes, int n_in,
                              void* d_out, int out_size) {
    const float* x     = (const float*)d_in[0];
    const float* rwpe  = (const float*)d_in[1];
    const float* W_rw  = (const float*)d_in[2];
    const float* b_rw  = (const float*)d_in[3];
    const float *Wc[5], *bc[5], *Wp[5], *bp[5];
    for (int i = 0; i < 5; i++) {
        Wc[i] = (const float*)d_in[4 + 4 * i];
        bc[i] = (const float*)d_in[5 + 4 * i];
        Wp[i] = (const float*)d_in[6 + 4 * i];
        bp[i] = (const float*)d_in[7 + 4 * i];
    }
    const float* gamma = (const float*)d_in[24];
    const float* beta  = (const float*)d_in[25];
    const int*   ei    = (const int*)d_in[26];
    const int*   ptr   = (const int*)d_in[27];
    float*       out   = (float*)d_out;
    const int* src = ei;
    const int* dst = ei + EE;

    float* h;
    __half2 *tH, *tP, *hp, *pe16;
    cudaGetSymbolAddress((void**)&h, g_h);
    cudaGetSymbolAddress((void**)&tH, g_tH);
    cudaGetSymbolAddress((void**)&tP, g_tP);
    cudaGetSymbolAddress((void**)&hp, g_hp);
    cudaGetSymbolAddress((void**)&pe16, g_pe16);

    // zero(1) -> deg(2) -> scan_part+dinv(3) -> fused gemm1(4, PROFILED)
    // -> scan_final(5) -> scatter(6) -> [aggr2 -> gemm16] x4 -> final -> bn -> pool
    k_zero<<<(NN + 255) / 256, 256>>>();                             // 1
    k_deg<<<(EE + 255) / 256, 256>>>(dst);                           // 2
    k_scan_part<<<49, 1024>>>();                                     // 3 (dinv)
    k_gemm1<<<2 * NB, 256>>>(x, rwpe, W_rw, b_rw,
                             Wc[0], tH, Wp[0], tP);                  // 4 (profiled)
    k_scan_final<<<49, 1024>>>();                                    // 5
    k_scatter<<<(EE + 255) / 256, 256>>>(src, dst);                  // 6

    for (int k = 0; k < 3; k++) {
        k_aggr2<<<AGB, 256>>>(tH, tP, bc[k], bp[k], hp, pe16);
        k_dualgemm16<true><<<2 * NB, 256>>>(hp, Wc[k + 1], tH,
                                            pe16, Wp[k + 1], tP);
    }
    k_aggr2<<<AGB, 256>>>(tH, tP, bc[3], bp[3], hp, pe16);
    k_dualgemm16<false><<<NB, 256>>>(hp, Wc[4], tH, nullptr, nullptr, nullptr);
    k_aggr_final<<<AGB, 256>>>(tH, bc[4], h);

    k_bn_stats<<<128, 256>>>(h);
    k_pool<<<GG, 256>>>(h, ptr, gamma, beta, out);
}